// round 7
// baseline (speedup 1.0000x reference)
#include <cuda_runtime.h>

// IFOPooling: h_t = f_t * h_{t-1} + i_t * z_t over seq (last dim, contiguous).
// [B=16, H=1024, S=2048] fp32 -> 16384 rows of 2048.
//
// R7: R6 per-row structure (TPB=256, EPT=8, 256-bit ld/st) + cross-row
// software pipelining: 2048 CTAs x 8 rows each; next row's loads are issued
// BEFORE the current row's scan/store, so reads stay in flight through the
// compute tail. Double-buffered smem aggregates -> one barrier per row.

#define SEQ   2048
#define TPB   256
#define EPT   8
#define ROWS  16384
#define GRID  2048
#define RPC   (ROWS / GRID)   // 8 rows per CTA

__device__ __forceinline__ void ldg256(const float* p, float r[8]) {
    asm volatile(
        "ld.global.L1::evict_first.v8.f32 {%0,%1,%2,%3,%4,%5,%6,%7}, [%8];"
        : "=f"(r[0]), "=f"(r[1]), "=f"(r[2]), "=f"(r[3]),
          "=f"(r[4]), "=f"(r[5]), "=f"(r[6]), "=f"(r[7])
        : "l"(p));
}

__device__ __forceinline__ void stg256(float* p, const float r[8]) {
    asm volatile(
        "st.global.L1::evict_first.v8.f32 [%0], {%1,%2,%3,%4,%5,%6,%7,%8};"
        :: "l"(p),
           "f"(r[0]), "f"(r[1]), "f"(r[2]), "f"(r[3]),
           "f"(r[4]), "f"(r[5]), "f"(r[6]), "f"(r[7])
        : "memory");
}

__global__ __launch_bounds__(TPB, 4) void ifo_scan_kernel(
    const float* __restrict__ f,
    const float* __restrict__ z,
    const float* __restrict__ ig,
    float* __restrict__ out)
{
    const int t    = threadIdx.x;
    const unsigned lane = t & 31u;
    const unsigned warp = t >> 5;

    __shared__ float sF[2][TPB / 32];
    __shared__ float sX[2][TPB / 32];

    int off = blockIdx.x * SEQ + t * EPT;

    // prologue: load row 0
    float fc[EPT], zc[EPT], ic[EPT];
    ldg256(f  + off, fc);
    ldg256(z  + off, zc);
    ldg256(ig + off, ic);

    #pragma unroll
    for (int it = 0; it < RPC; it++) {
        const int buf = it & 1;
        const int noff = off + GRID * SEQ;

        // ---- prefetch next row (independent of everything below) ----
        float fn[EPT], zn[EPT], in_[EPT];
        if (it + 1 < RPC) {
            ldg256(f  + noff, fn);
            ldg256(z  + noff, zn);
            ldg256(ig + noff, in_);
        }

        // ---- local segment composite on current row ----
        float xv[EPT];
        #pragma unroll
        for (int j = 0; j < EPT; j++) xv[j] = ic[j] * zc[j];

        float F = 1.0f, X = 0.0f;
        #pragma unroll
        for (int j = 0; j < EPT; j++) {
            X = fmaf(fc[j], X, xv[j]);
            F *= fc[j];
        }

        // ---- inclusive warp scan of composites ----
        float Fs = F, Xs = X;
        #pragma unroll
        for (int d = 1; d < 32; d <<= 1) {
            float Fo = __shfl_up_sync(0xFFFFFFFFu, Fs, d);
            float Xo = __shfl_up_sync(0xFFFFFFFFu, Xs, d);
            if (lane >= (unsigned)d) {
                Xs = fmaf(Fs, Xo, Xs);   // (Fo,Xo) then (Fs,Xs)
                Fs = Fs * Fo;
            }
        }

        // warp aggregates -> double-buffered smem; one barrier per row
        if (lane == 31) { sF[buf][warp] = Fs; sX[buf][warp] = Xs; }
        __syncthreads();

        float Xc = 0.0f;
        #pragma unroll
        for (int w = 0; w < TPB / 32; w++) {
            if (w < (int)warp) Xc = fmaf(sF[buf][w], Xc, sX[buf][w]);
        }

        float Fex = __shfl_up_sync(0xFFFFFFFFu, Fs, 1);
        float Xex = __shfl_up_sync(0xFFFFFFFFu, Xs, 1);
        if (lane == 0) { Fex = 1.0f; Xex = 0.0f; }

        float h = fmaf(Fex, Xc, Xex);

        // ---- replay, 256-bit store ----
        float r[EPT];
        #pragma unroll
        for (int j = 0; j < EPT; j++) {
            h = fmaf(fc[j], h, xv[j]);
            r[j] = h;
        }
        stg256(out + off, r);

        // ---- rotate buffers (renamed away by unroll) ----
        if (it + 1 < RPC) {
            #pragma unroll
            for (int j = 0; j < EPT; j++) {
                fc[j] = fn[j]; zc[j] = zn[j]; ic[j] = in_[j];
            }
        }
        off = noff;
    }
}

extern "C" void kernel_launch(void* const* d_in, const int* in_sizes, int n_in,
                              void* d_out, int out_size)
{
    const float* f  = (const float*)d_in[0];
    const float* z  = (const float*)d_in[1];
    const float* ig = (const float*)d_in[2];
    float* out = (float*)d_out;

    ifo_scan_kernel<<<GRID, TPB>>>(f, z, ig, out);
}

// round 8
// speedup vs baseline: 1.0972x; 1.0972x over previous
#include <cuda_runtime.h>

// IFOPooling: h_t = f_t * h_{t-1} + i_t * z_t over seq (last dim, contiguous).
// [B=16, H=1024, S=2048] fp32 -> 16384 rows of 2048.
//
// R8: R4 shape (block-per-row, TPB=128, EPT=16) rebuilt on 256-bit ld/st.
// R4's limiter was L1tex wavefront-queue saturation from 12x LDG.128/thread;
// v8 accesses halve that (6x LDG.256 + 2x STG.256). Only 4 warp aggregates
// in the smem phase.

#define SEQ 2048
#define TPB 128
#define EPT 16   // elements per thread

__device__ __forceinline__ void ldg256(const float* p, float r[8]) {
    asm volatile(
        "ld.global.L1::evict_first.v8.f32 {%0,%1,%2,%3,%4,%5,%6,%7}, [%8];"
        : "=f"(r[0]), "=f"(r[1]), "=f"(r[2]), "=f"(r[3]),
          "=f"(r[4]), "=f"(r[5]), "=f"(r[6]), "=f"(r[7])
        : "l"(p));
}

__device__ __forceinline__ void stg256(float* p, const float r[8]) {
    asm volatile(
        "st.global.L1::evict_first.v8.f32 [%0], {%1,%2,%3,%4,%5,%6,%7,%8};"
        :: "l"(p),
           "f"(r[0]), "f"(r[1]), "f"(r[2]), "f"(r[3]),
           "f"(r[4]), "f"(r[5]), "f"(r[6]), "f"(r[7])
        : "memory");
}

__global__ __launch_bounds__(TPB) void ifo_scan_kernel(
    const float* __restrict__ f,
    const float* __restrict__ z,
    const float* __restrict__ ig,
    float* __restrict__ out)
{
    const int row  = blockIdx.x;
    const int base = row * SEQ;
    const int t    = threadIdx.x;
    const int off  = base + t * EPT;

    // ---- Phase 1: 6 front-batched 256-bit loads ----
    float fv[EPT], zv[EPT], iv[EPT];
    ldg256(f  + off,     fv);
    ldg256(f  + off + 8, fv + 8);
    ldg256(z  + off,     zv);
    ldg256(z  + off + 8, zv + 8);
    ldg256(ig + off,     iv);
    ldg256(ig + off + 8, iv + 8);

    float xv[EPT];
    #pragma unroll
    for (int j = 0; j < EPT; j++) xv[j] = iv[j] * zv[j];

    // local segment composite (F, X): h_out = F*h_in + X
    float F = 1.0f, X = 0.0f;
    #pragma unroll
    for (int j = 0; j < EPT; j++) {
        X = fmaf(fv[j], X, xv[j]);
        F *= fv[j];
    }

    // ---- Phase 2: inclusive warp scan of composites ----
    const unsigned lane = t & 31u;
    const unsigned warp = t >> 5;
    float Fs = F, Xs = X;
    #pragma unroll
    for (int d = 1; d < 32; d <<= 1) {
        float Fo = __shfl_up_sync(0xFFFFFFFFu, Fs, d);
        float Xo = __shfl_up_sync(0xFFFFFFFFu, Xs, d);
        if (lane >= (unsigned)d) {
            Xs = fmaf(Fs, Xo, Xs);   // (Fo,Xo) then (Fs,Xs)
            Fs = Fs * Fo;
        }
    }

    // warp aggregates -> smem (4 warps)
    __shared__ float sF[TPB / 32];
    __shared__ float sX[TPB / 32];
    if (lane == 31) { sF[warp] = Fs; sX[warp] = Xs; }
    __syncthreads();

    // carry from preceding warps (<= 3 fmas)
    float Xc = 0.0f;
    #pragma unroll
    for (int w = 0; w < TPB / 32; w++) {
        if (w < (int)warp) Xc = fmaf(sF[w], Xc, sX[w]);
    }

    // exclusive-within-warp composite = inclusive of lane-1
    float Fex = __shfl_up_sync(0xFFFFFFFFu, Fs, 1);
    float Xex = __shfl_up_sync(0xFFFFFFFFu, Xs, 1);
    if (lane == 0) { Fex = 1.0f; Xex = 0.0f; }

    float h = fmaf(Fex, Xc, Xex);

    // ---- Phase 3: replay, two 256-bit stores ----
    float r[EPT];
    #pragma unroll
    for (int j = 0; j < EPT; j++) {
        h = fmaf(fv[j], h, xv[j]);
        r[j] = h;
    }
    stg256(out + off,     r);
    stg256(out + off + 8, r + 8);
}

extern "C" void kernel_launch(void* const* d_in, const int* in_sizes, int n_in,
                              void* d_out, int out_size)
{
    const float* f  = (const float*)d_in[0];
    const float* z  = (const float*)d_in[1];
    const float* ig = (const float*)d_in[2];
    float* out = (float*)d_out;

    const int rows = out_size / SEQ;   // 16384
    ifo_scan_kernel<<<rows, TPB>>>(f, z, ig, out);
}